// round 14
// baseline (speedup 1.0000x reference)
#include <cuda_runtime.h>
#include <cuda_fp16.h>
#include <math.h>

#define S     512
#define E     256
#define H2    512
#define HC    1024
#define VOCAB 50257
#define GRID  148
#define NT    512
#define CBLK  340            // vocab cols per CTA block
#define CPAD  352            // padded row stride (halfs)
#define PR    16             // k-rows per warp held permanently in SMEM
#define DYNB  (16 * PR * CPAD * 2)   // 180224 B dynamic smem

// ---------------- device scratch (static globals; no allocation) ----------------
__device__ __half g_linTh[(size_t)GRID * 1024 * CPAD];  // blocked transposed fp16 lin_W (~107MB)
__device__ float g_emb[S*E];
__device__ int   g_mask[S];
__device__ float g_ehf[2][E];
__device__ float g_ehb[2][E];
__device__ float g_outf[S*E];
__device__ float g_outb[S*E];
__device__ float g_encT[H2*S];
__device__ float g_A[S*H2];
__device__ float g_dvec[S];
__device__ float g_enchid[H2];
__device__ float g_dh[2][H2];
__device__ float g_scores[S];
__device__ float g_ctx[H2];
__device__ float g_z[HC];
__device__ float g_pval[GRID];
__device__ int   g_pidx[GRID];
// generation-counting barriers: monotonic, replay-safe (A = gen*N, R = gen at launch exit)
__device__ unsigned long long g_bA, g_bR;        // full grid (148)
__device__ unsigned long long g_sA, g_sR;        // small grid (CTAs 0-31)
__device__ unsigned long long g_eA[2], g_eR[2];  // encoder (64 each)

__device__ __forceinline__ float sigf(float x) { return 1.f / (1.f + expf(-x)); }

__device__ __forceinline__ void gbar_n(unsigned long long* A, unsigned long long* R, unsigned n) {
    __syncthreads();
    if (threadIdx.x == 0) {
        __threadfence();
        unsigned long long pos = atomicAdd(A, 1ULL);
        unsigned long long gen = pos / n;
        if (pos - gen * n == n - 1ULL) {
            __threadfence();
            atomicAdd(R, 1ULL);
        } else {
            unsigned long long r;
            do { asm volatile("ld.acquire.gpu.u64 %0, [%1];" : "=l"(r) : "l"(R) : "memory"); } while (r <= gen);
        }
    }
    __syncthreads();
}
__device__ __forceinline__ void gbar()   { gbar_n(&g_bA, &g_bR, GRID); }
__device__ __forceinline__ void gbar32() { gbar_n(&g_sA, &g_sR, 32u); }

// L2 evict_last hint
__device__ __forceinline__ unsigned long long mk_evict_last() {
    unsigned long long p;
    asm("createpolicy.fractional.L2::evict_last.b64 %0, 1.0;" : "=l"(p));
    return p;
}
__device__ __forceinline__ uint4 ldg_el_u4(const uint4* p, unsigned long long pol) {
    uint4 v;
    asm volatile("ld.global.nc.L2::cache_hint.v4.u32 {%0,%1,%2,%3}, [%4], %5;"
                 : "=r"(v.x), "=r"(v.y), "=r"(v.z), "=r"(v.w)
                 : "l"(p), "l"(pol));
    return v;
}

// half2 fma: uint4 = 8 halfs, accumulate in half2 (no converts on the hot path)
__device__ __forceinline__ void fma_h8h(__half2* h, uint4 p, __half2 zh) {
    h[0] = __hfma2(*reinterpret_cast<const __half2*>(&p.x), zh, h[0]);
    h[1] = __hfma2(*reinterpret_cast<const __half2*>(&p.y), zh, h[1]);
    h[2] = __hfma2(*reinterpret_cast<const __half2*>(&p.z), zh, h[2]);
    h[3] = __hfma2(*reinterpret_cast<const __half2*>(&p.w), zh, h[3]);
}
// flush half2 chunk accumulators into fp32 and reset (every 16 rows)
__device__ __forceinline__ void flush_h(__half2* h, float* a) {
    #pragma unroll
    for (int j = 0; j < 4; j++) {
        float2 f = __half22float2(h[j]);
        a[2 * j]     += f.x;
        a[2 * j + 1] += f.y;
        h[j] = __float2half2_rn(0.f);
    }
}

// Prefetch rows PR..63 of this warp's k-chunk into L2 (idle-window prefetch).
__device__ __forceinline__ void prefetch_slab(const __half* slab, int warp, int lane) {
    const char* base = (const char*)(slab + (size_t)(warp * 64 + PR) * CPAD);
    const int lines = (64 - PR) * 704 / 128;   // 264 lines of 128B
    #pragma unroll 4
    for (int i = lane; i < lines; i += 32)
        asm volatile("prefetch.global.L2 [%0];" :: "l"(base + (size_t)i * 128));
}

__global__ void __launch_bounds__(NT, 1) seq2seq_kernel(
    const int*   __restrict__ tokens,
    const float* __restrict__ enc_emb,
    const float* __restrict__ dec_emb,
    const float* __restrict__ eWi_f, const float* __restrict__ eWh_f, const float* __restrict__ eb_f,
    const float* __restrict__ eWi_b, const float* __restrict__ eWh_b, const float* __restrict__ eb_b,
    const float* __restrict__ dWi,   const float* __restrict__ dWh,   const float* __restrict__ db,
    const float* __restrict__ attn_W, const float* __restrict__ attn_b,
    const float* __restrict__ W_W,    const float* __restrict__ W_b,
    const float* __restrict__ lin_W,  const float* __restrict__ lin_b,
    float* __restrict__ out, int sent_off)
{
    extern __shared__ __half dynsm[];    // persistent slab slice: 16 warps x PR rows x CPAD
    __shared__ float s_a[HC];            // 4KB
    __shared__ float s_b[H2];            // 2KB
    __shared__ float s_part[16 * CPAD];  // 22.5KB (also reused as transpose tile)
    __shared__ float s_rv[16];
    __shared__ int   s_ri[16];
    __shared__ float s_red[32];
    __shared__ float s_ec[4];
    __shared__ int   s_word;
    __shared__ int   s_cand[2];
    __shared__ float s_cve[2];

    const int cta = blockIdx.x, tid = threadIdx.x;
    const int warp = tid >> 5, lane = tid & 31;
    float* out_logits = out + (sent_off ? (S + 1) : 0);
    const __half* myslab = g_linTh + (size_t)cta * (1024 * CPAD);
    const unsigned long long pol = mk_evict_last();
    float c_state = 0.f;                 // decoder LSTM cell state (lane 0, CTAs 0-31)

    // ---------- phase T: transpose own lin_W block into fp16 g_linTh ----------
    {
        float (*tile)[33] = (float (*)[33])s_part;   // 32x33
        const int x = lane, y = warp;                // y: 0..15
        __half* dst = g_linTh + (size_t)cta * (1024 * CPAD);
        for (int kt = 0; kt < 1024; kt += 32) {
            for (int ct = 0; ct < CPAD; ct += 32) {
                #pragma unroll
                for (int yy = 0; yy < 2; yy++) {
                    int c   = ct + y + 16 * yy;
                    int row = cta * CBLK + c;
                    float v = 0.f;
                    if (c < CBLK && row < VOCAB) v = __ldg(lin_W + (size_t)row * HC + kt + x);
                    tile[y + 16 * yy][x] = v;
                }
                __syncthreads();
                #pragma unroll
                for (int yy = 0; yy < 2; yy++) {
                    int k = kt + y + 16 * yy;
                    dst[(size_t)k * CPAD + ct + x] = __float2half_rn(tile[x][y + 16 * yy]);
                }
                __syncthreads();
            }
        }
    }
    // persistent SMEM copy: first PR rows of each warp's 64-row chunk
    {
        const uint4* src = (const uint4*)(myslab + (size_t)(warp * 64) * CPAD);
        uint4* dst = (uint4*)(dynsm + (size_t)warp * (PR * CPAD));
        for (int i = lane; i < PR * CPAD / 8; i += 32) dst[i] = src[i];
    }

    // ---------- setup ----------
    for (int idx = cta * NT + tid; idx < S * E; idx += GRID * NT) {
        int t = idx / E, k = idx - t * E;
        g_emb[idx] = fmaxf(__ldg(enc_emb + (size_t)tokens[t] * E + k), 0.f);
    }
    for (int idx = cta * NT + tid; idx < S; idx += GRID * NT) g_mask[idx] = tokens[idx] > 0;
    for (int idx = cta * NT + tid; idx < E; idx += GRID * NT) { g_ehf[1][idx] = 0.f; g_ehb[1][idx] = 0.f; }
    if (tid < 4) s_ec[tid] = 0.f;
    gbar();

    // ---------- encoder BiLSTM: CTAs 0..63 fwd, 64..127 bwd ----------
    if (cta < 128) {
        const int dir   = cta >> 6;
        const int ubase = (cta & 63) * 4;
        const float* Wi = dir ? eWi_b : eWi_f;
        const float* Wh = dir ? eWh_b : eWh_f;
        const float* bb = dir ? eb_b  : eb_f;
        const int u = warp >> 2, gg = warp & 3;
        const int row = gg * E + (ubase + u);
        const float4* wi4 = (const float4*)(Wi + (size_t)row * E);
        const float4* wh4 = (const float4*)(Wh + (size_t)row * E);
        const float brow = __ldg(bb + row);
        for (int t = 0; t < S; t++) {
            const int xt = dir ? (S - 1 - t) : t;
            const float* hrd = dir ? g_ehb[(t ^ 1) & 1] : g_ehf[(t ^ 1) & 1];
            if (tid < E) { s_a[tid] = g_emb[xt * E + tid]; s_b[tid] = hrd[tid]; }
            __syncthreads();
            const float4* a4 = (const float4*)s_a;
            const float4* b4 = (const float4*)s_b;
            float acc = 0.f;
            #pragma unroll
            for (int i = 0; i < 2; i++) {
                float4 w = __ldg(wi4 + lane + 32 * i); float4 v = a4[lane + 32 * i];
                acc += w.x*v.x + w.y*v.y + w.z*v.z + w.w*v.w;
                float4 w2 = __ldg(wh4 + lane + 32 * i); float4 v2 = b4[lane + 32 * i];
                acc += w2.x*v2.x + w2.y*v2.y + w2.z*v2.z + w2.w*v2.w;
            }
            #pragma unroll
            for (int o = 16; o; o >>= 1) acc += __shfl_down_sync(0xffffffffu, acc, o);
            if (lane == 0) s_red[warp] = acc + brow;
            __syncthreads();
            if (tid < 4) {
                float gi = s_red[tid*4+0], gf = s_red[tid*4+1], gc = s_red[tid*4+2], go = s_red[tid*4+3];
                float c = sigf(gf) * s_ec[tid] + sigf(gi) * tanhf(gc);
                float h = sigf(go) * tanhf(c);
                s_ec[tid] = c;
                int uj = ubase + tid;
                (dir ? g_ehb[t & 1] : g_ehf[t & 1])[uj] = h;
                (dir ? g_outb : g_outf)[xt * E + uj]   = h;
            }
            gbar_n(&g_eA[dir], &g_eR[dir], 64u);
        }
    }
    gbar();

    // ---------- setup2: encT, A, dvec, enc_hidden ----------
    for (int idx = cta * NT + tid; idx < H2 * S; idx += GRID * NT) {
        int k = idx / S, s = idx - k * S;
        float v = (k < E) ? g_outf[s * E + k] : g_outb[s * E + (k - E)];
        g_encT[idx] = g_mask[s] ? v : 0.f;
    }
    for (int s = cta; s < S; s += GRID) {
        float m = g_mask[s] ? 1.f : 0.f;
        for (int j = tid; j < H2; j += NT)
            s_b[j] = ((j < E) ? g_outf[s * E + j] : g_outb[s * E + j - E]) * m;
        __syncthreads();
        if (tid < H2) {
            const int k = tid;
            float acc = 0.f;
            #pragma unroll 4
            for (int j = 0; j < H2; j++) acc += s_b[j] * __ldg(attn_W + j * H2 + k);
            g_A[s * H2 + k] = acc;
        }
        if (tid == 0) {
            float acc = 0.f;
            for (int j = 0; j < H2; j++) acc += s_b[j] * __ldg(attn_b + j);
            g_dvec[s] = acc;
        }
        __syncthreads();
    }
    if (cta == 0) {
        for (int j = tid; j < E; j += NT) {
            float hf = g_outf[(S - 1) * E + j];
            float hb = g_outb[0 * E + j];
            g_enchid[j]     = hf; g_enchid[E + j] = hb;
            g_dh[1][j]      = hf; g_dh[1][E + j]  = hb;
        }
        if (tid == 0 && sent_off) out[0] = 1.0f;   // SOS
    }
    if (tid == 0) s_word = 1;                       // SOS
    gbar();

    // ---------- autoregressive decode, 512 steps ----------
    for (int t = 0; t < S; t++) {
        if (cta < 32) {
            // Phase G: decoder LSTM — warp owns one unit, computes all 4 gates
            {
                const int w = s_word;
                if (tid < H2) {
                    s_a[tid]      = fmaxf(__ldg(dec_emb + (size_t)w * H2 + tid), 0.f);
                    s_a[H2 + tid] = g_enchid[tid];
                    s_b[tid]      = g_dh[(t ^ 1) & 1][tid];
                }
                __syncthreads();
                const int unit = cta * 16 + warp;         // 0..511
                const float4* a4 = (const float4*)s_a;
                const float4* b4 = (const float4*)s_b;
                float acc[4];
                #pragma unroll
                for (int g = 0; g < 4; g++) {
                    const float4* wi4 = (const float4*)(dWi + (size_t)(g * H2 + unit) * HC);
                    const float4* wh4 = (const float4*)(dWh + (size_t)(g * H2 + unit) * H2);
                    float a = 0.f;
                    #pragma unroll
                    for (int i = 0; i < 8; i++) {
                        float4 wv = __ldg(wi4 + lane + 32 * i); float4 av = a4[lane + 32 * i];
                        a += wv.x*av.x + wv.y*av.y + wv.z*av.z + wv.w*av.w;
                    }
                    #pragma unroll
                    for (int i = 0; i < 4; i++) {
                        float4 wv = __ldg(wh4 + lane + 32 * i); float4 bv = b4[lane + 32 * i];
                        a += wv.x*bv.x + wv.y*bv.y + wv.z*bv.z + wv.w*bv.w;
                    }
                    #pragma unroll
                    for (int o = 16; o; o >>= 1) a += __shfl_down_sync(0xffffffffu, a, o);
                    acc[g] = a;
                }
                if (lane == 0) {
                    float gi = acc[0] + __ldg(db + unit);
                    float gf = acc[1] + __ldg(db + H2 + unit);
                    float gc = acc[2] + __ldg(db + 2 * H2 + unit);
                    float go = acc[3] + __ldg(db + 3 * H2 + unit);
                    c_state = sigf(gf) * c_state + sigf(gi) * tanhf(gc);
                    g_dh[t & 1][unit] = sigf(go) * tanhf(c_state);
                }
            }
            gbar32();

            // Phase S: scores = A @ h + d (warp-per-score)
            {
                const int gw = cta * 16 + warp;
                const float4* Ar4 = (const float4*)(g_A + (size_t)gw * H2);
                const float4* hv4 = (const float4*)(g_dh[t & 1]);
                float acc = 0.f;
                #pragma unroll
                for (int i = 0; i < 4; i++) {
                    float4 a = __ldg(Ar4 + lane + 32 * i);
                    float4 h = hv4[lane + 32 * i];
                    acc += a.x*h.x + a.y*h.y + a.z*h.z + a.w*h.w;
                }
                #pragma unroll
                for (int o = 16; o; o >>= 1) acc += __shfl_down_sync(0xffffffffu, acc, o);
                if (lane == 0) {
                    float sc = acc + g_dvec[gw];
                    g_scores[gw] = g_mask[gw] ? sc : -INFINITY;
                }
            }
            gbar32();

            // Phase C: redundant softmax + context
            {
                s_b[tid] = g_scores[tid];
                __syncthreads();
                float m = s_b[tid];
                #pragma unroll
                for (int o = 16; o; o >>= 1) m = fmaxf(m, __shfl_down_sync(0xffffffffu, m, o));
                if (lane == 0) s_red[warp] = m;
                __syncthreads();
                if (tid == 0) {
                    float mm = s_red[0];
                    #pragma unroll
                    for (int i = 1; i < 16; i++) mm = fmaxf(mm, s_red[i]);
                    s_red[16] = mm;
                }
                __syncthreads();
                const float mx = s_red[16];
                float e = (mx == -INFINITY) ? 0.f : expf(s_b[tid] - mx);
                float sum = e;
                #pragma unroll
                for (int o = 16; o; o >>= 1) sum += __shfl_down_sync(0xffffffffu, sum, o);
                if (lane == 0) s_red[warp] = sum;
                __syncthreads();
                if (tid == 0) {
                    float ss = 0.f;
                    #pragma unroll
                    for (int i = 0; i < 16; i++) ss += s_red[i];
                    s_red[17] = (ss > 0.f) ? 1.f / ss : 0.f;
                }
                __syncthreads();
                s_b[tid] = e * s_red[17];
                __syncthreads();
                const int gw = cta * 16 + warp;           // 0..511
                const float4* et4 = (const float4*)(g_encT + (size_t)gw * S);
                const float4* w4  = (const float4*)s_b;
                float acc = 0.f;
                #pragma unroll
                for (int i = 0; i < 4; i++) {
                    float4 ev = __ldg(et4 + lane + 32 * i);
                    float4 wv = w4[lane + 32 * i];
                    acc += ev.x*wv.x + ev.y*wv.y + ev.z*wv.z + ev.w*wv.w;
                }
                #pragma unroll
                for (int o = 16; o; o >>= 1) acc += __shfl_down_sync(0xffffffffu, acc, o);
                if (lane == 0) g_ctx[gw] = acc;
            }
            gbar32();

            // Phase Z: z = [h, ctx] @ W_W^T + W_b (2 rows per warp)
            {
                if (tid < H2) {
                    s_a[tid]      = g_dh[t & 1][tid];
                    s_a[H2 + tid] = g_ctx[tid];
                }
                __syncthreads();
                const float4* a4 = (const float4*)s_a;
                #pragma unroll
                for (int rr = 0; rr < 2; rr++) {
                    const int gw = cta * 16 + warp + rr * 512;   // 0..1023
                    const float4* ww4 = (const float4*)(W_W + (size_t)gw * HC);
                    float acc = 0.f;
                    #pragma unroll
                    for (int i = 0; i < 8; i++) {
                        float4 w = __ldg(ww4 + lane + 32 * i);
                        float4 v = a4[lane + 32 * i];
                        acc += w.x*v.x + w.y*v.y + w.z*v.z + w.w*v.w;
                    }
                    #pragma unroll
                    for (int o = 16; o; o >>= 1) acc += __shfl_down_sync(0xffffffffu, acc, o);
                    if (lane == 0) g_z[gw] = acc + __ldg(W_b + gw);
                }
            }
        } else {
            // Idle CTAs: prefetch the global portion of their slab into L2.
            prefetch_slab(myslab, warp, lane);
        }
        gbar();   // z ready, slab prefetch drained

        // Phase L: fp16 logits GEMV — HFMA2 chunked accumulation (flush every 16 rows)
        {
            for (int i = tid; i < HC; i += NT) s_a[i] = g_z[i];
            __syncthreads();
            const float* zw = s_a + warp * 64;
            const bool has2 = lane < 12;                  // cols 256..351
            const uint4 zq = make_uint4(0u, 0u, 0u, 0u);
            const __half2 hz = __float2half2_rn(0.f);
            float a0[8], a1[8];
            __half2 h0[4], h1[4];
            #pragma unroll
            for (int j = 0; j < 8; j++) { a0[j] = 0.f; a1[j] = 0.f; }
            #pragma unroll
            for (int j = 0; j < 4; j++) { h0[j] = hz; h1[j] = hz; }

            // issue first global preloads early (latency overlaps smem compute)
            const __half* wb = myslab + (size_t)(warp * 64 + PR) * CPAD;
            uint4 c00 = ldg_el_u4((const uint4*)wb + lane, pol);
            uint4 c01 = has2 ? ldg_el_u4((const uint4*)(wb + 256) + lane, pol) : zq;
            uint4 c10 = ldg_el_u4((const uint4*)(wb + CPAD) + lane, pol);
            uint4 c11 = has2 ? ldg_el_u4((const uint4*)(wb + CPAD + 256) + lane, pol) : zq;

            // SMEM rows 0..PR-1 (one 16-row chunk)
            const __half* sm = dynsm + (size_t)warp * (PR * CPAD);
            #pragma unroll 4
            for (int k = 0; k < PR; k++) {
                __half2 zh = __float2half2_rn(zw[k]);
                uint4 s0 = ((const uint4*)(sm + k * CPAD))[lane];
                fma_h8h(h0, s0, zh);
                if (has2) {
                    uint4 s1 = ((const uint4*)(sm + k * CPAD + 256))[lane];
                    fma_h8h(h1, s1, zh);
                }
            }
            flush_h(h0, a0); flush_h(h1, a1);

            // global rows PR..63 (48 rows = 3 chunks of 16), depth-2 pipeline
            const float* zg = zw + PR;
            #pragma unroll 1
            for (int k = 0; k < 46; k += 2) {
                const __half* r2 = wb + (size_t)(k + 2) * CPAD;
                uint4 n00 = ldg_el_u4((const uint4*)r2 + lane, pol);
                uint4 n01 = has2 ? ldg_el_u4((const uint4*)(r2 + 256) + lane, pol) : zq;
                __half2 zh0 = __float2half2_rn(zg[k]);
                fma_h8h(h0, c00, zh0); fma_h8h(h1, c01, zh0);
                c00 = n00; c01 = n01;
                const __half* r3 = wb + (size_t)(k + 3) * CPAD;
                uint4 n10 = ldg_el_u4((const uint4*)r3 + lane, pol);
                uint4 n11 = has2 ? ldg_el_u4((const uint4*)(r3 + 256) + lane, pol) : zq;
                __half2 zh1 = __float2half2_rn(zg[k + 1]);
                fma_h8h(h0, c10, zh1); fma_h8h(h1, c11, zh1);
                c10 = n10; c11 = n11;
                if ((k & 15) == 14) { flush_h(h0, a0); flush_h(h1, a1); }   // after rows 15, 31
            }
            {
                __half2 zh0 = __float2half2_rn(zg[46]);
                fma_h8h(h0, c00, zh0); fma_h8h(h1, c01, zh0);
                __half2 zh1 = __float2half2_rn(zg[47]);
                fma_h8h(h0, c10, zh1); fma_h8h(h1, c11, zh1);
                flush_h(h0, a0); flush_h(h1, a1);                            // rows 32..47
            }

            float4* sp = (float4*)(s_part + warp * CPAD + lane * 8);
            sp[0] = make_float4(a0[0], a0[1], a0[2], a0[3]);
            sp[1] = make_float4(a0[4], a0[5], a0[6], a0[7]);
            if (has2) {
                float4* sp2 = (float4*)(s_part + warp * CPAD + 256 + lane * 8);
                sp2[0] = make_float4(a1[0], a1[1], a1[2], a1[3]);
                sp2[1] = make_float4(a1[4], a1[5], a1[6], a1[7]);
            }
            __syncthreads();
            const int base = cta * CBLK;
            const int ncol = min(CBLK, VOCAB - base);
            float* olog = out_logits + (size_t)t * VOCAB;
            float myv = -INFINITY;
            if (tid < ncol) {
                float sum = 0.f;
                #pragma unroll
                for (int w = 0; w < 16; w++) sum += s_part[w * CPAD + tid];
                myv = sum + __ldg(lin_b + base + tid);
                __stcs(olog + base + tid, myv);
            }
            // approx top-1
            float bv = myv; int bi = (tid < ncol) ? (base + tid) : 0x7fffffff;
            #pragma unroll
            for (int o = 16; o; o >>= 1) {
                float ov = __shfl_down_sync(0xffffffffu, bv, o);
                int   oi = __shfl_down_sync(0xffffffffu, bi, o);
                if (ov > bv || (ov == bv && oi < bi)) { bv = ov; bi = oi; }
            }
            if (lane == 0) { s_rv[warp] = bv; s_ri[warp] = bi; }
            __syncthreads();
            if (warp == 0) {
                float v = (lane < 16) ? s_rv[lane] : -INFINITY;
                int  ii = (lane < 16) ? s_ri[lane] : 0x7fffffff;
                #pragma unroll
                for (int o = 8; o; o >>= 1) {
                    float ov = __shfl_down_sync(0xffffffffu, v, o);
                    int   oi = __shfl_down_sync(0xffffffffu, ii, o);
                    if (ov > v || (ov == v && oi < ii)) { v = ov; ii = oi; }
                }
                if (lane == 0) s_cand[0] = ii;
            }
            __syncthreads();
            // approx top-2 (exclude top-1)
            const int ex = s_cand[0];
            float bv2 = (tid < ncol && (base + tid) != ex) ? myv : -INFINITY;
            int   bi2 = (tid < ncol && (base + tid) != ex) ? (base + tid) : 0x7fffffff;
            #pragma unroll
            for (int o = 16; o; o >>= 1) {
                float ov = __shfl_down_sync(0xffffffffu, bv2, o);
                int   oi = __shfl_down_sync(0xffffffffu, bi2, o);
                if (ov > bv2 || (ov == bv2 && oi < bi2)) { bv2 = ov; bi2 = oi; }
            }
            if (lane == 0) { s_rv[warp] = bv2; s_ri[warp] = bi2; }
            __syncthreads();
            if (warp == 0) {
                float v = (lane < 16) ? s_rv[lane] : -INFINITY;
                int  ii = (lane < 16) ? s_ri[lane] : 0x7fffffff;
                #pragma unroll
                for (int o = 8; o; o >>= 1) {
                    float ov = __shfl_down_sync(0xffffffffu, v, o);
                    int   oi = __shfl_down_sync(0xffffffffu, ii, o);
                    if (ov > v || (ov == v && oi < ii)) { v = ov; ii = oi; }
                }
                if (lane == 0) s_cand[1] = ii;
            }
            __syncthreads();
            // exact fp32 rescore of the two candidates
            if (warp < 2) {
                const int row = s_cand[warp];
                const float4* wr = (const float4*)(lin_W + (size_t)row * HC);
                const float4* z4 = (const float4*)s_a;
                float acc = 0.f;
                #pragma unroll
                for (int j = 0; j < 8; j++) {
                    float4 w = __ldg(wr + lane + 32 * j);
                    float4 zz = z4[lane + 32 * j];
                    acc += w.x*zz.x + w.y*zz.y + w.z*zz.z + w.w*zz.w;
                }
                #pragma unroll
                for (int o = 16; o; o >>= 1) acc += __shfl_down_sync(0xffffffffu, acc, o);
                if (lane == 0) s_cve[warp] = acc + __ldg(lin_b + row);
            }
            __syncthreads();
            if (tid == 0) {
                float v0 = s_cve[0], v1 = s_cve[1];
                int   i0 = s_cand[0], i1 = s_cand[1];
                if (v1 > v0 || (v1 == v0 && i1 < i0)) { v0 = v1; i0 = i1; }
                g_pval[cta] = v0; g_pidx[cta] = i0;
            }
        }
        gbar();

        // Phase R: warp-parallel global argmax -> next word
        if (warp == 0) {
            float v = -INFINITY; int ii = 0x7fffffff;
            #pragma unroll
            for (int i = 0; i < 5; i++) {
                int idx = lane + 32 * i;
                if (idx < GRID) {
                    float pv = g_pval[idx]; int pi = g_pidx[idx];
                    if (pv > v || (pv == v && pi < ii)) { v = pv; ii = pi; }
                }
            }
            #pragma unroll
            for (int o = 16; o; o >>= 1) {
                float ov = __shfl_down_sync(0xffffffffu, v, o);
                int   oi = __shfl_down_sync(0xffffffffu, ii, o);
                if (ov > v || (ov == v && oi < ii)) { v = ov; ii = oi; }
            }
            if (lane == 0) {
                s_word = ii;
                if (cta == 0 && sent_off) out[1 + t] = (float)ii;
            }
        }
        __syncthreads();
    }
}

extern "C" void kernel_launch(void* const* d_in, const int* in_sizes, int n_in,
                              void* d_out, int out_size)
{
    const int*   tokens  = (const int*)  d_in[0];
    const float* enc_emb = (const float*)d_in[2];
    const float* dec_emb = (const float*)d_in[3];
    const float* eWi_f   = (const float*)d_in[4];
    const float* eWh_f   = (const float*)d_in[5];
    const float* eb_f    = (const float*)d_in[6];
    const float* eWi_b   = (const float*)d_in[7];
    const float* eWh_b   = (const float*)d_in[8];
    const float* eb_b    = (const float*)d_in[9];
    const float* dWi     = (const float*)d_in[10];
    const float* dWh     = (const float*)d_in[11];
    const float* db      = (const float*)d_in[12];
    const float* attn_W  = (const float*)d_in[13];
    const float* attn_b  = (const float*)d_in[14];
    const float* W_W     = (const float*)d_in[15];
    const float* W_b     = (const float*)d_in[16];
    const float* lin_W   = (const float*)d_in[17];
    const float* lin_b   = (const float*)d_in[18];

    long long need_full = (long long)(S + 1) + (long long)S * VOCAB;
    int sent_off = ((long long)out_size >= need_full) ? 1 : 0;

    cudaFuncSetAttribute(seq2seq_kernel, cudaFuncAttributeMaxDynamicSharedMemorySize, DYNB);
    seq2seq_kernel<<<GRID, NT, DYNB>>>(tokens, enc_emb, dec_emb,
                                       eWi_f, eWh_f, eb_f, eWi_b, eWh_b, eb_b,
                                       dWi, dWh, db, attn_W, attn_b, W_W, W_b,
                                       lin_W, lin_b, (float*)d_out, sent_off);
}

// round 15
// speedup vs baseline: 1.0354x; 1.0354x over previous
#include <cuda_runtime.h>
#include <cuda_fp16.h>
#include <math.h>

#define S     512
#define E     256
#define H2    512
#define HC    1024
#define VOCAB 50257
#define GRID  148
#define NT    512
#define CBLK  340            // vocab cols per CTA block
#define CPAD  352            // padded row stride (halfs)
#define PR    16             // k-rows per warp held permanently in SMEM
#define DYNB  (16 * PR * CPAD * 2)   // 180224 B dynamic smem

// ---------------- device scratch (static globals; no allocation) ----------------
__device__ __half g_linTh[(size_t)GRID * 1024 * CPAD];  // blocked transposed fp16 lin_W (~107MB)
__device__ float g_emb[S*E];
__device__ int   g_mask[S];
__device__ float g_ehf[2][E];
__device__ float g_ehb[2][E];
__device__ float g_outf[S*E];
__device__ float g_outb[S*E];
__device__ float g_encT[H2*S];
__device__ float g_A[S*H2];
__device__ float g_dvec[S];
__device__ float g_enchid[H2];
__device__ float g_dh[2][H2];
__device__ float g_scores[S];
__device__ float g_ctx[H2];
__device__ float g_z[HC];
__device__ float g_pval[GRID];
__device__ int   g_pidx[GRID];
// generation-counting barriers: monotonic, replay-safe (A = gen*N, R = gen at launch exit)
__device__ unsigned long long g_bA, g_bR;        // full grid (148)
__device__ unsigned long long g_sA, g_sR;        // small grid (CTAs 0-31)
__device__ unsigned long long g_eA[2], g_eR[2];  // encoder (64 each)

__device__ __forceinline__ float sigf(float x) { return 1.f / (1.f + expf(-x)); }

__device__ __forceinline__ void gbar_n(unsigned long long* A, unsigned long long* R, unsigned n) {
    __syncthreads();
    if (threadIdx.x == 0) {
        __threadfence();
        unsigned long long pos = atomicAdd(A, 1ULL);
        unsigned long long gen = pos / n;
        if (pos - gen * n == n - 1ULL) {
            __threadfence();
            atomicAdd(R, 1ULL);
        } else {
            unsigned long long r;
            do { asm volatile("ld.acquire.gpu.u64 %0, [%1];" : "=l"(r) : "l"(R) : "memory"); } while (r <= gen);
        }
    }
    __syncthreads();
}
__device__ __forceinline__ void gbar()   { gbar_n(&g_bA, &g_bR, GRID); }
__device__ __forceinline__ void gbar32() { gbar_n(&g_sA, &g_sR, 32u); }

// L2 evict_last hint
__device__ __forceinline__ unsigned long long mk_evict_last() {
    unsigned long long p;
    asm("createpolicy.fractional.L2::evict_last.b64 %0, 1.0;" : "=l"(p));
    return p;
}
__device__ __forceinline__ uint4 ldg_el_u4(const uint4* p, unsigned long long pol) {
    uint4 v;
    asm volatile("ld.global.nc.L2::cache_hint.v4.u32 {%0,%1,%2,%3}, [%4], %5;"
                 : "=r"(v.x), "=r"(v.y), "=r"(v.z), "=r"(v.w)
                 : "l"(p), "l"(pol));
    return v;
}

// half2 fma: uint4 = 8 halfs, accumulate in half2 (no converts on the hot path)
__device__ __forceinline__ void fma_h8h(__half2* h, uint4 p, __half2 zh) {
    h[0] = __hfma2(*reinterpret_cast<const __half2*>(&p.x), zh, h[0]);
    h[1] = __hfma2(*reinterpret_cast<const __half2*>(&p.y), zh, h[1]);
    h[2] = __hfma2(*reinterpret_cast<const __half2*>(&p.z), zh, h[2]);
    h[3] = __hfma2(*reinterpret_cast<const __half2*>(&p.w), zh, h[3]);
}
// flush half2 chunk accumulators into fp32 and reset (every 16 rows)
__device__ __forceinline__ void flush_h(__half2* h, float* a) {
    #pragma unroll
    for (int j = 0; j < 4; j++) {
        float2 f = __half22float2(h[j]);
        a[2 * j]     += f.x;
        a[2 * j + 1] += f.y;
        h[j] = __float2half2_rn(0.f);
    }
}

// Prefetch rows PR..63 of this warp's k-chunk into L2 (idle-window prefetch).
__device__ __forceinline__ void prefetch_slab(const __half* slab, int warp, int lane) {
    const char* base = (const char*)(slab + (size_t)(warp * 64 + PR) * CPAD);
    const int lines = (64 - PR) * 704 / 128;   // 264 lines of 128B
    #pragma unroll 4
    for (int i = lane; i < lines; i += 32)
        asm volatile("prefetch.global.L2 [%0];" :: "l"(base + (size_t)i * 128));
}

__global__ void __launch_bounds__(NT, 1) seq2seq_kernel(
    const int*   __restrict__ tokens,
    const float* __restrict__ enc_emb,
    const float* __restrict__ dec_emb,
    const float* __restrict__ eWi_f, const float* __restrict__ eWh_f, const float* __restrict__ eb_f,
    const float* __restrict__ eWi_b, const float* __restrict__ eWh_b, const float* __restrict__ eb_b,
    const float* __restrict__ dWi,   const float* __restrict__ dWh,   const float* __restrict__ db,
    const float* __restrict__ attn_W, const float* __restrict__ attn_b,
    const float* __restrict__ W_W,    const float* __restrict__ W_b,
    const float* __restrict__ lin_W,  const float* __restrict__ lin_b,
    float* __restrict__ out, int sent_off)
{
    extern __shared__ __half dynsm[];    // persistent slab slice: 16 warps x PR rows x CPAD
    __shared__ float s_a[HC];            // 4KB
    __shared__ float s_b[H2];            // 2KB
    __shared__ float s_part[16 * CPAD];  // 22.5KB (also reused as transpose tile)
    __shared__ float s_rv[16];
    __shared__ int   s_ri[16];
    __shared__ float s_red[32];
    __shared__ float s_ec[4];
    __shared__ int   s_word;
    __shared__ int   s_cand[2];
    __shared__ float s_cve[2];

    const int cta = blockIdx.x, tid = threadIdx.x;
    const int warp = tid >> 5, lane = tid & 31;
    float* out_logits = out + (sent_off ? (S + 1) : 0);
    const __half* myslab = g_linTh + (size_t)cta * (1024 * CPAD);
    const unsigned long long pol = mk_evict_last();
    float c_state = 0.f;                 // decoder LSTM cell state (lane 0, CTAs 0-31)

    // ---------- phase T: transpose own lin_W block into fp16 g_linTh ----------
    {
        float (*tile)[33] = (float (*)[33])s_part;   // 32x33
        const int x = lane, y = warp;                // y: 0..15
        __half* dst = g_linTh + (size_t)cta * (1024 * CPAD);
        for (int kt = 0; kt < 1024; kt += 32) {
            for (int ct = 0; ct < CPAD; ct += 32) {
                #pragma unroll
                for (int yy = 0; yy < 2; yy++) {
                    int c   = ct + y + 16 * yy;
                    int row = cta * CBLK + c;
                    float v = 0.f;
                    if (c < CBLK && row < VOCAB) v = __ldg(lin_W + (size_t)row * HC + kt + x);
                    tile[y + 16 * yy][x] = v;
                }
                __syncthreads();
                #pragma unroll
                for (int yy = 0; yy < 2; yy++) {
                    int k = kt + y + 16 * yy;
                    dst[(size_t)k * CPAD + ct + x] = __float2half_rn(tile[x][y + 16 * yy]);
                }
                __syncthreads();
            }
        }
    }
    // persistent SMEM copy: first PR rows of each warp's 64-row chunk
    {
        const uint4* src = (const uint4*)(myslab + (size_t)(warp * 64) * CPAD);
        uint4* dst = (uint4*)(dynsm + (size_t)warp * (PR * CPAD));
        for (int i = lane; i < PR * CPAD / 8; i += 32) dst[i] = src[i];
    }

    // ---------- setup ----------
    for (int idx = cta * NT + tid; idx < S * E; idx += GRID * NT) {
        int t = idx / E, k = idx - t * E;
        g_emb[idx] = fmaxf(__ldg(enc_emb + (size_t)tokens[t] * E + k), 0.f);
    }
    for (int idx = cta * NT + tid; idx < S; idx += GRID * NT) g_mask[idx] = tokens[idx] > 0;
    for (int idx = cta * NT + tid; idx < E; idx += GRID * NT) { g_ehf[1][idx] = 0.f; g_ehb[1][idx] = 0.f; }
    if (tid < 4) s_ec[tid] = 0.f;
    gbar();

    // ---------- encoder BiLSTM: CTAs 0..63 fwd, 64..127 bwd ----------
    if (cta < 128) {
        const int dir   = cta >> 6;
        const int ubase = (cta & 63) * 4;
        const float* Wi = dir ? eWi_b : eWi_f;
        const float* Wh = dir ? eWh_b : eWh_f;
        const float* bb = dir ? eb_b  : eb_f;
        const int u = warp >> 2, gg = warp & 3;
        const int row = gg * E + (ubase + u);
        const float4* wi4 = (const float4*)(Wi + (size_t)row * E);
        const float4* wh4 = (const float4*)(Wh + (size_t)row * E);
        const float brow = __ldg(bb + row);
        for (int t = 0; t < S; t++) {
            const int xt = dir ? (S - 1 - t) : t;
            const float* hrd = dir ? g_ehb[(t ^ 1) & 1] : g_ehf[(t ^ 1) & 1];
            if (tid < E) { s_a[tid] = g_emb[xt * E + tid]; s_b[tid] = hrd[tid]; }
            __syncthreads();
            const float4* a4 = (const float4*)s_a;
            const float4* b4 = (const float4*)s_b;
            float acc = 0.f;
            #pragma unroll
            for (int i = 0; i < 2; i++) {
                float4 w = __ldg(wi4 + lane + 32 * i); float4 v = a4[lane + 32 * i];
                acc += w.x*v.x + w.y*v.y + w.z*v.z + w.w*v.w;
                float4 w2 = __ldg(wh4 + lane + 32 * i); float4 v2 = b4[lane + 32 * i];
                acc += w2.x*v2.x + w2.y*v2.y + w2.z*v2.z + w2.w*v2.w;
            }
            #pragma unroll
            for (int o = 16; o; o >>= 1) acc += __shfl_down_sync(0xffffffffu, acc, o);
            if (lane == 0) s_red[warp] = acc + brow;
            __syncthreads();
            if (tid < 4) {
                float gi = s_red[tid*4+0], gf = s_red[tid*4+1], gc = s_red[tid*4+2], go = s_red[tid*4+3];
                float c = sigf(gf) * s_ec[tid] + sigf(gi) * tanhf(gc);
                float h = sigf(go) * tanhf(c);
                s_ec[tid] = c;
                int uj = ubase + tid;
                (dir ? g_ehb[t & 1] : g_ehf[t & 1])[uj] = h;
                (dir ? g_outb : g_outf)[xt * E + uj]   = h;
            }
            gbar_n(&g_eA[dir], &g_eR[dir], 64u);
        }
    }
    gbar();

    // ---------- setup2: encT, A, dvec, enc_hidden ----------
    for (int idx = cta * NT + tid; idx < H2 * S; idx += GRID * NT) {
        int k = idx / S, s = idx - k * S;
        float v = (k < E) ? g_outf[s * E + k] : g_outb[s * E + (k - E)];
        g_encT[idx] = g_mask[s] ? v : 0.f;
    }
    for (int s = cta; s < S; s += GRID) {
        float m = g_mask[s] ? 1.f : 0.f;
        for (int j = tid; j < H2; j += NT)
            s_b[j] = ((j < E) ? g_outf[s * E + j] : g_outb[s * E + j - E]) * m;
        __syncthreads();
        if (tid < H2) {
            const int k = tid;
            float acc = 0.f;
            #pragma unroll 4
            for (int j = 0; j < H2; j++) acc += s_b[j] * __ldg(attn_W + j * H2 + k);
            g_A[s * H2 + k] = acc;
        }
        if (tid == 0) {
            float acc = 0.f;
            for (int j = 0; j < H2; j++) acc += s_b[j] * __ldg(attn_b + j);
            g_dvec[s] = acc;
        }
        __syncthreads();
    }
    if (cta == 0) {
        for (int j = tid; j < E; j += NT) {
            float hf = g_outf[(S - 1) * E + j];
            float hb = g_outb[0 * E + j];
            g_enchid[j]     = hf; g_enchid[E + j] = hb;
            g_dh[1][j]      = hf; g_dh[1][E + j]  = hb;
        }
        if (tid == 0 && sent_off) out[0] = 1.0f;   // SOS
    }
    if (tid == 0) s_word = 1;                       // SOS
    gbar();

    // ---------- autoregressive decode, 512 steps ----------
    for (int t = 0; t < S; t++) {
        if (cta < 32) {
            // Phase G: decoder LSTM — warp owns one unit, computes all 4 gates
            {
                const int w = s_word;
                if (tid < H2) {
                    s_a[tid]      = fmaxf(__ldg(dec_emb + (size_t)w * H2 + tid), 0.f);
                    s_a[H2 + tid] = g_enchid[tid];
                    s_b[tid]      = g_dh[(t ^ 1) & 1][tid];
                }
                __syncthreads();
                const int unit = cta * 16 + warp;         // 0..511
                const float4* a4 = (const float4*)s_a;
                const float4* b4 = (const float4*)s_b;
                float acc[4];
                #pragma unroll
                for (int g = 0; g < 4; g++) {
                    const float4* wi4 = (const float4*)(dWi + (size_t)(g * H2 + unit) * HC);
                    const float4* wh4 = (const float4*)(dWh + (size_t)(g * H2 + unit) * H2);
                    float a = 0.f;
                    #pragma unroll
                    for (int i = 0; i < 8; i++) {
                        float4 wv = __ldg(wi4 + lane + 32 * i); float4 av = a4[lane + 32 * i];
                        a += wv.x*av.x + wv.y*av.y + wv.z*av.z + wv.w*av.w;
                    }
                    #pragma unroll
                    for (int i = 0; i < 4; i++) {
                        float4 wv = __ldg(wh4 + lane + 32 * i); float4 bv = b4[lane + 32 * i];
                        a += wv.x*bv.x + wv.y*bv.y + wv.z*bv.z + wv.w*bv.w;
                    }
                    #pragma unroll
                    for (int o = 16; o; o >>= 1) a += __shfl_down_sync(0xffffffffu, a, o);
                    acc[g] = a;
                }
                if (lane == 0) {
                    float gi = acc[0] + __ldg(db + unit);
                    float gf = acc[1] + __ldg(db + H2 + unit);
                    float gc = acc[2] + __ldg(db + 2 * H2 + unit);
                    float go = acc[3] + __ldg(db + 3 * H2 + unit);
                    c_state = sigf(gf) * c_state + sigf(gi) * tanhf(gc);
                    g_dh[t & 1][unit] = sigf(go) * tanhf(c_state);
                }
            }
            gbar32();

            // Phase S: scores = A @ h + d (warp-per-score)
            {
                const int gw = cta * 16 + warp;
                const float4* Ar4 = (const float4*)(g_A + (size_t)gw * H2);
                const float4* hv4 = (const float4*)(g_dh[t & 1]);
                float acc = 0.f;
                #pragma unroll
                for (int i = 0; i < 4; i++) {
                    float4 a = __ldg(Ar4 + lane + 32 * i);
                    float4 h = hv4[lane + 32 * i];
                    acc += a.x*h.x + a.y*h.y + a.z*h.z + a.w*h.w;
                }
                #pragma unroll
                for (int o = 16; o; o >>= 1) acc += __shfl_down_sync(0xffffffffu, acc, o);
                if (lane == 0) {
                    float sc = acc + g_dvec[gw];
                    g_scores[gw] = g_mask[gw] ? sc : -INFINITY;
                }
            }
            gbar32();

            // Phase C: redundant softmax + context
            {
                s_b[tid] = g_scores[tid];
                __syncthreads();
                float m = s_b[tid];
                #pragma unroll
                for (int o = 16; o; o >>= 1) m = fmaxf(m, __shfl_down_sync(0xffffffffu, m, o));
                if (lane == 0) s_red[warp] = m;
                __syncthreads();
                if (tid == 0) {
                    float mm = s_red[0];
                    #pragma unroll
                    for (int i = 1; i < 16; i++) mm = fmaxf(mm, s_red[i]);
                    s_red[16] = mm;
                }
                __syncthreads();
                const float mx = s_red[16];
                float e = (mx == -INFINITY) ? 0.f : expf(s_b[tid] - mx);
                float sum = e;
                #pragma unroll
                for (int o = 16; o; o >>= 1) sum += __shfl_down_sync(0xffffffffu, sum, o);
                if (lane == 0) s_red[warp] = sum;
                __syncthreads();
                if (tid == 0) {
                    float ss = 0.f;
                    #pragma unroll
                    for (int i = 0; i < 16; i++) ss += s_red[i];
                    s_red[17] = (ss > 0.f) ? 1.f / ss : 0.f;
                }
                __syncthreads();
                s_b[tid] = e * s_red[17];
                __syncthreads();
                const int gw = cta * 16 + warp;           // 0..511
                const float4* et4 = (const float4*)(g_encT + (size_t)gw * S);
                const float4* w4  = (const float4*)s_b;
                float acc = 0.f;
                #pragma unroll
                for (int i = 0; i < 4; i++) {
                    float4 ev = __ldg(et4 + lane + 32 * i);
                    float4 wv = w4[lane + 32 * i];
                    acc += ev.x*wv.x + ev.y*wv.y + ev.z*wv.z + ev.w*wv.w;
                }
                #pragma unroll
                for (int o = 16; o; o >>= 1) acc += __shfl_down_sync(0xffffffffu, acc, o);
                if (lane == 0) g_ctx[gw] = acc;
            }
            gbar32();

            // Phase Z: z = [h, ctx] @ W_W^T + W_b (2 rows per warp)
            {
                if (tid < H2) {
                    s_a[tid]      = g_dh[t & 1][tid];
                    s_a[H2 + tid] = g_ctx[tid];
                }
                __syncthreads();
                const float4* a4 = (const float4*)s_a;
                #pragma unroll
                for (int rr = 0; rr < 2; rr++) {
                    const int gw = cta * 16 + warp + rr * 512;   // 0..1023
                    const float4* ww4 = (const float4*)(W_W + (size_t)gw * HC);
                    float acc = 0.f;
                    #pragma unroll
                    for (int i = 0; i < 8; i++) {
                        float4 w = __ldg(ww4 + lane + 32 * i);
                        float4 v = a4[lane + 32 * i];
                        acc += w.x*v.x + w.y*v.y + w.z*v.z + w.w*v.w;
                    }
                    #pragma unroll
                    for (int o = 16; o; o >>= 1) acc += __shfl_down_sync(0xffffffffu, acc, o);
                    if (lane == 0) g_z[gw] = acc + __ldg(W_b + gw);
                }
            }
        } else {
            // Idle CTAs: prefetch the global portion of their slab into L2.
            prefetch_slab(myslab, warp, lane);
        }
        gbar();   // z ready, slab prefetch drained

        // Phase L: fp16 logits GEMV — HFMA2 chunked accumulation (flush every 16 rows)
        {
            for (int i = tid; i < HC; i += NT) s_a[i] = g_z[i];
            __syncthreads();
            const float* zw = s_a + warp * 64;
            const bool has2 = lane < 12;                  // cols 256..351
            const uint4 zq = make_uint4(0u, 0u, 0u, 0u);
            const __half2 hz = __float2half2_rn(0.f);
            float a0[8], a1[8];
            __half2 h0[4], h1[4];
            #pragma unroll
            for (int j = 0; j < 8; j++) { a0[j] = 0.f; a1[j] = 0.f; }
            #pragma unroll
            for (int j = 0; j < 4; j++) { h0[j] = hz; h1[j] = hz; }

            // issue first global preloads early (latency overlaps smem compute)
            const __half* wb = myslab + (size_t)(warp * 64 + PR) * CPAD;
            uint4 c00 = ldg_el_u4((const uint4*)wb + lane, pol);
            uint4 c01 = has2 ? ldg_el_u4((const uint4*)(wb + 256) + lane, pol) : zq;
            uint4 c10 = ldg_el_u4((const uint4*)(wb + CPAD) + lane, pol);
            uint4 c11 = has2 ? ldg_el_u4((const uint4*)(wb + CPAD + 256) + lane, pol) : zq;

            // SMEM rows 0..PR-1 (one 16-row chunk)
            const __half* sm = dynsm + (size_t)warp * (PR * CPAD);
            #pragma unroll 4
            for (int k = 0; k < PR; k++) {
                __half2 zh = __float2half2_rn(zw[k]);
                uint4 s0 = ((const uint4*)(sm + k * CPAD))[lane];
                fma_h8h(h0, s0, zh);
                if (has2) {
                    uint4 s1 = ((const uint4*)(sm + k * CPAD + 256))[lane];
                    fma_h8h(h1, s1, zh);
                }
            }
            flush_h(h0, a0); flush_h(h1, a1);

            // global rows PR..63 (48 rows = 3 chunks of 16), depth-2 pipeline
            const float* zg = zw + PR;
            #pragma unroll 1
            for (int k = 0; k < 46; k += 2) {
                const __half* r2 = wb + (size_t)(k + 2) * CPAD;
                uint4 n00 = ldg_el_u4((const uint4*)r2 + lane, pol);
                uint4 n01 = has2 ? ldg_el_u4((const uint4*)(r2 + 256) + lane, pol) : zq;
                __half2 zh0 = __float2half2_rn(zg[k]);
                fma_h8h(h0, c00, zh0); fma_h8h(h1, c01, zh0);
                c00 = n00; c01 = n01;
                const __half* r3 = wb + (size_t)(k + 3) * CPAD;
                uint4 n10 = ldg_el_u4((const uint4*)r3 + lane, pol);
                uint4 n11 = has2 ? ldg_el_u4((const uint4*)(r3 + 256) + lane, pol) : zq;
                __half2 zh1 = __float2half2_rn(zg[k + 1]);
                fma_h8h(h0, c10, zh1); fma_h8h(h1, c11, zh1);
                c10 = n10; c11 = n11;
                if ((k & 15) == 14) { flush_h(h0, a0); flush_h(h1, a1); }   // after rows 15, 31
            }
            {
                __half2 zh0 = __float2half2_rn(zg[46]);
                fma_h8h(h0, c00, zh0); fma_h8h(h1, c01, zh0);
                __half2 zh1 = __float2half2_rn(zg[47]);
                fma_h8h(h0, c10, zh1); fma_h8h(h1, c11, zh1);
                flush_h(h0, a0); flush_h(h1, a1);                            // rows 32..47
            }

            float4* sp = (float4*)(s_part + warp * CPAD + lane * 8);
            sp[0] = make_float4(a0[0], a0[1], a0[2], a0[3]);
            sp[1] = make_float4(a0[4], a0[5], a0[6], a0[7]);
            if (has2) {
                float4* sp2 = (float4*)(s_part + warp * CPAD + 256 + lane * 8);
                sp2[0] = make_float4(a1[0], a1[1], a1[2], a1[3]);
                sp2[1] = make_float4(a1[4], a1[5], a1[6], a1[7]);
            }
            __syncthreads();
            const int base = cta * CBLK;
            const int ncol = min(CBLK, VOCAB - base);
            float* olog = out_logits + (size_t)t * VOCAB;
            float myv = -INFINITY;
            if (tid < ncol) {
                float sum = 0.f;
                #pragma unroll
                for (int w = 0; w < 16; w++) sum += s_part[w * CPAD + tid];
                myv = sum + __ldg(lin_b + base + tid);
                __stcs(olog + base + tid, myv);
            }
            // approx top-1
            float bv = myv; int bi = (tid < ncol) ? (base + tid) : 0x7fffffff;
            #pragma unroll
            for (int o = 16; o; o >>= 1) {
                float ov = __shfl_down_sync(0xffffffffu, bv, o);
                int   oi = __shfl_down_sync(0xffffffffu, bi, o);
                if (ov > bv || (ov == bv && oi < bi)) { bv = ov; bi = oi; }
            }
            if (lane == 0) { s_rv[warp] = bv; s_ri[warp] = bi; }
            __syncthreads();
            if (warp == 0) {
                float v = (lane < 16) ? s_rv[lane] : -INFINITY;
                int  ii = (lane < 16) ? s_ri[lane] : 0x7fffffff;
                #pragma unroll
                for (int o = 8; o; o >>= 1) {
                    float ov = __shfl_down_sync(0xffffffffu, v, o);
                    int   oi = __shfl_down_sync(0xffffffffu, ii, o);
                    if (ov > v || (ov == v && oi < ii)) { v = ov; ii = oi; }
                }
                if (lane == 0) s_cand[0] = ii;
            }
            __syncthreads();
            // approx top-2 (exclude top-1)
            const int ex = s_cand[0];
            float bv2 = (tid < ncol && (base + tid) != ex) ? myv : -INFINITY;
            int   bi2 = (tid < ncol && (base + tid) != ex) ? (base + tid) : 0x7fffffff;
            #pragma unroll
            for (int o = 16; o; o >>= 1) {
                float ov = __shfl_down_sync(0xffffffffu, bv2, o);
                int   oi = __shfl_down_sync(0xffffffffu, bi2, o);
                if (ov > bv2 || (ov == bv2 && oi < bi2)) { bv2 = ov; bi2 = oi; }
            }
            if (lane == 0) { s_rv[warp] = bv2; s_ri[warp] = bi2; }
            __syncthreads();
            if (warp == 0) {
                float v = (lane < 16) ? s_rv[lane] : -INFINITY;
                int  ii = (lane < 16) ? s_ri[lane] : 0x7fffffff;
                #pragma unroll
                for (int o = 8; o; o >>= 1) {
                    float ov = __shfl_down_sync(0xffffffffu, v, o);
                    int   oi = __shfl_down_sync(0xffffffffu, ii, o);
                    if (ov > v || (ov == v && oi < ii)) { v = ov; ii = oi; }
                }
                if (lane == 0) s_cand[1] = ii;
            }
            __syncthreads();
            // exact fp32 rescore of the two candidates
            if (warp < 2) {
                const int row = s_cand[warp];
                const float4* wr = (const float4*)(lin_W + (size_t)row * HC);
                const float4* z4 = (const float4*)s_a;
                float acc = 0.f;
                #pragma unroll
                for (int j = 0; j < 8; j++) {
                    float4 w = __ldg(wr + lane + 32 * j);
                    float4 zz = z4[lane + 32 * j];
                    acc += w.x*zz.x + w.y*zz.y + w.z*zz.z + w.w*zz.w;
                }
                #pragma unroll
                for (int o = 16; o; o >>= 1) acc += __shfl_down_sync(0xffffffffu, acc, o);
                if (lane == 0) s_cve[warp] = acc + __ldg(lin_b + row);
            }
            __syncthreads();
            if (tid == 0) {
                float v0 = s_cve[0], v1 = s_cve[1];
                int   i0 = s_cand[0], i1 = s_cand[1];
                if (v1 > v0 || (v1 == v0 && i1 < i0)) { v0 = v1; i0 = i1; }
                g_pval[cta] = v0; g_pidx[cta] = i0;
            }
        }
        gbar();

        // Phase R: warp-parallel global argmax -> next word
        if (warp == 0) {
            float v = -INFINITY; int ii = 0x7fffffff;
            #pragma unroll
            for (int i = 0; i < 5; i++) {
                int idx = lane + 32 * i;
                if (idx < GRID) {
                    float pv = g_pval[idx]; int pi = g_pidx[idx];
                    if (pv > v || (pv == v && pi < ii)) { v = pv; ii = pi; }
                }
            }
            #pragma unroll
            for (int o = 16; o; o >>= 1) {
                float ov = __shfl_down_sync(0xffffffffu, v, o);
                int   oi = __shfl_down_sync(0xffffffffu, ii, o);
                if (ov > v || (ov == v && oi < ii)) { v = ov; ii = oi; }
            }
            if (lane == 0) {
                s_word = ii;
                if (cta == 0 && sent_off) out[1 + t] = (float)ii;
            }
        }
        __syncthreads();
    }
}

extern "C" void kernel_launch(void* const* d_in, const int* in_sizes, int n_in,
                              void* d_out, int out_size)
{
    const int*   tokens  = (const int*)  d_in[0];
    const float* enc_emb = (const float*)d_in[2];
    const float* dec_emb = (const float*)d_in[3];
    const float* eWi_f   = (const float*)d_in[4];
    const float* eWh_f   = (const float*)d_in[5];
    const float* eb_f    = (const float*)d_in[6];
    const float* eWi_b   = (const float*)d_in[7];
    const float* eWh_b   = (const float*)d_in[8];
    const float* eb_b    = (const float*)d_in[9];
    const float* dWi     = (const float*)d_in[10];
    const float* dWh     = (const float*)d_in[11];
    const float* db      = (const float*)d_in[12];
    const float* attn_W  = (const float*)d_in[13];
    const float* attn_b  = (const float*)d_in[14];
    const float* W_W     = (const float*)d_in[15];
    const float* W_b     = (const float*)d_in[16];
    const float* lin_W   = (const float*)d_in[17];
    const float* lin_b   = (const float*)d_in[18];

    long long need_full = (long long)(S + 1) + (long long)S * VOCAB;
    int sent_off = ((long long)out_size >= need_full) ? 1 : 0;

    cudaFuncSetAttribute(seq2seq_kernel, cudaFuncAttributeMaxDynamicSharedMemorySize, DYNB);
    seq2seq_kernel<<<GRID, NT, DYNB>>>(tokens, enc_emb, dec_emb,
                                       eWi_f, eWh_f, eb_f, eWi_b, eWh_b, eb_b,
                                       dWi, dWh, db, attn_W, attn_b, W_W, W_b,
                                       lin_W, lin_b, (float*)d_out, sent_off);
}